// round 1
// baseline (speedup 1.0000x reference)
#include <cuda_runtime.h>

// Problem constants (fixed shapes from reference)
#define HH 256
#define WW 512
#define HW (HH * WW)            // 131072 = 2^17
#define NSTUFF 11
#define NBOX 128
#define STUFF_ELEMS (NSTUFF * HW)  // 1,441,792 (divisible by 4)

__global__ __launch_bounds__(256) void seg_term_kernel(
    const int*    __restrict__ cls,     // [128]
    const float*  __restrict__ seg,     // [19*HW]
    const float*  __restrict__ boxes,   // [128*5]
    float*        __restrict__ out,     // [STUFF_ELEMS + 128*HW]
    int total4)
{
    int i = blockIdx.x * blockDim.x + threadIdx.x;
    if (i >= total4) return;

    long long e = (long long)i * 4;

    if (e < (long long)STUFF_ELEMS) {
        // seg_stuff_energy = seg_score[:, :11] verbatim copy
        const float4* s4 = reinterpret_cast<const float4*>(seg);
        float4* o4 = reinterpret_cast<float4*>(out);
        o4[i] = s4[i];
        return;
    }

    // Instance-energy region
    int r = (int)(e - STUFF_ELEMS);     // < 128*HW = 2^24, fits int
    int n = r >> 17;                    // box index
    int p = r & (HW - 1);               // pixel within channel plane
    int y = p >> 9;                     // row
    int x = p & (WW - 1);               // col (first of 4 consecutive)

    float4 v = make_float4(0.f, 0.f, 0.f, 0.f);

    int c = cls[n];
    if (c != 0) {
        const float* b = boxes + n * 5;
        float bx0 = b[1] * 0.25f;
        float by0 = b[2] * 0.25f;
        float bx1 = b[3] * 0.25f;
        float by1 = b[4] * 0.25f;

        int x0 = (int)floorf(bx0);
        int y0 = (int)floorf(by0);
        int x1 = (int)(rintf(bx1) + 1.0f);   // rintf = round-half-even, matches jnp.round
        int y1 = (int)(rintf(by1) + 1.0f);

        if (y >= y0 && y < y1) {
            int m = c + 10;
            m = (m > 18) ? 18 : m;           // clip to NUM_SEG_CLASSES-1
            const float* srow = seg + m * HW + p;   // 16B-aligned (p % 4 == 0)

            if (x >= x0 && (x + 3) < x1) {
                // fully inside: vectorized gather
                v = *reinterpret_cast<const float4*>(srow);
            } else if ((x + 3) >= x0 && x < x1) {
                // straddles an edge: per-lane mask
                float vv[4];
                #pragma unroll
                for (int j = 0; j < 4; j++) {
                    int xx = x + j;
                    vv[j] = (xx >= x0 && xx < x1) ? srow[j] : 0.f;
                }
                v = make_float4(vv[0], vv[1], vv[2], vv[3]);
            }
            // else: entirely outside → zeros
        }
    }

    reinterpret_cast<float4*>(out)[i] = v;
}

extern "C" void kernel_launch(void* const* d_in, const int* in_sizes, int n_in,
                              void* d_out, int out_size)
{
    const int*   cls   = (const int*)d_in[0];     // cls_indices int32[128]
    const float* seg   = (const float*)d_in[1];   // seg_score f32[1,19,256,512]
    const float* boxes = (const float*)d_in[2];   // boxes f32[128,5]
    float* out = (float*)d_out;

    int total4 = out_size / 4;                    // 4,554,752 float4 stores
    int threads = 256;
    int blocks = (total4 + threads - 1) / threads;

    seg_term_kernel<<<blocks, threads>>>(cls, seg, boxes, out, total4);
}

// round 2
// speedup vs baseline: 1.2474x; 1.2474x over previous
#include <cuda_runtime.h>

// Fixed shapes
#define HH 256
#define WW 512
#define HW (HH * WW)                 // 131072 = 2^17 floats/plane
#define HW4 (HW / 4)                 // 32768 float4/plane
#define W4 (WW / 4)                  // 128 float4/row
#define NSTUFF 11
#define STUFF4 (NSTUFF * HW4)        // 360448 float4
#define ITEMS 4                      // float4 per thread
#define TPB 256
#define F4_PER_BLK (TPB * ITEMS)     // 1024 float4 per block
#define STUFF_BLOCKS (STUFF4 / F4_PER_BLK)   // 352 (exact)
#define BLOCKS_PER_PLANE (HW4 / F4_PER_BLK)  // 32 (exact)
#define NBOX 128

__global__ __launch_bounds__(TPB) void seg_term_kernel(
    const int*    __restrict__ cls,     // [128]
    const float*  __restrict__ seg,     // [19*HW]
    const float*  __restrict__ boxes,   // [128*5]
    float*        __restrict__ out)     // [STUFF4*4 + 128*HW]
{
    const int b = blockIdx.x;
    const int tid = threadIdx.x;

    if (b < STUFF_BLOCKS) {
        // ---- stuff copy: seg_score[:, :11] verbatim, 4 float4 per thread ----
        const float4* s4 = reinterpret_cast<const float4*>(seg);
        float4*       o4 = reinterpret_cast<float4*>(out);
        int base = b * F4_PER_BLK + tid;
        #pragma unroll
        for (int k = 0; k < ITEMS; k++)
            o4[base + k * TPB] = s4[base + k * TPB];
        return;
    }

    // ---- instance region: each block owns 1024 float4 of ONE plane ----
    const int ib  = b - STUFF_BLOCKS;
    const int n   = ib >> 5;                 // box/plane index (32 blocks per plane)
    const int blk = ib & (BLOCKS_PER_PLANE - 1);

    float4* o4 = reinterpret_cast<float4*>(out) + STUFF4 + n * HW4 + blk * F4_PER_BLK;

    const float4 z = make_float4(0.f, 0.f, 0.f, 0.f);

    const int c = __ldg(cls + n);
    if (c == 0) {
        // whole plane is zero
        #pragma unroll
        for (int k = 0; k < ITEMS; k++)
            o4[tid + k * TPB] = z;
        return;
    }

    // Box bounds — uniform across the block (L1 broadcast loads)
    const float* bb = boxes + n * 5;
    const int x0 = (int)floorf(__ldg(bb + 1) * 0.25f);
    const int y0 = (int)floorf(__ldg(bb + 2) * 0.25f);
    const int x1 = (int)(rintf(__ldg(bb + 3) * 0.25f) + 1.0f);  // matches jnp.round (half-even)
    const int y1 = (int)(rintf(__ldg(bb + 4) * 0.25f) + 1.0f);

    int m = c + 10;
    m = (m > 18) ? 18 : m;
    const float4* s4 = reinterpret_cast<const float4*>(seg) + m * HW4 + blk * F4_PER_BLK;

    #pragma unroll
    for (int k = 0; k < ITEMS; k++) {
        const int idx = tid + k * TPB;               // float4 index within chunk
        const int p4  = blk * F4_PER_BLK + idx;      // float4 index within plane
        const int y   = p4 >> 7;                     // row (128 float4/row)
        const int x   = (p4 & (W4 - 1)) << 2;        // first col of this float4

        float4 v = z;
        if (y >= y0 && y < y1) {
            if (x >= x0 && (x + 3) < x1) {
                v = s4[idx];                         // fully inside: vector gather
            } else if ((x + 3) >= x0 && x < x1) {
                const float* sr = reinterpret_cast<const float*>(s4 + idx);
                float vv[4];
                #pragma unroll
                for (int j = 0; j < 4; j++) {
                    const int xx = x + j;
                    vv[j] = (xx >= x0 && xx < x1) ? sr[j] : 0.f;
                }
                v = make_float4(vv[0], vv[1], vv[2], vv[3]);
            }
        }
        o4[idx] = v;
    }
}

extern "C" void kernel_launch(void* const* d_in, const int* in_sizes, int n_in,
                              void* d_out, int out_size)
{
    const int*   cls   = (const int*)d_in[0];
    const float* seg   = (const float*)d_in[1];
    const float* boxes = (const float*)d_in[2];
    float* out = (float*)d_out;

    const int blocks = STUFF_BLOCKS + NBOX * BLOCKS_PER_PLANE;  // 352 + 4096 = 4448
    seg_term_kernel<<<blocks, TPB>>>(cls, seg, boxes, out);
}

// round 3
// speedup vs baseline: 1.2959x; 1.0389x over previous
#include <cuda_runtime.h>

// Fixed shapes
#define HH 256
#define WW 512
#define HW (HH * WW)                 // 131072 floats/plane
#define HW4 (HW / 4)                 // 32768 float4/plane
#define W4 (WW / 4)                  // 128 float4/row
#define NSTUFF 11
#define STUFF4 (NSTUFF * HW4)        // 360448 float4
#define ITEMS 8                      // float4 per thread
#define TPB 256
#define F4_PER_BLK (TPB * ITEMS)     // 2048 float4 per block (= 16 rows)
#define ROWS_PER_BLK (F4_PER_BLK / W4)       // 16
#define STUFF_BLOCKS (STUFF4 / F4_PER_BLK)   // 176 (exact)
#define BLOCKS_PER_PLANE (HW4 / F4_PER_BLK)  // 16 (exact)
#define NBOX 128

__global__ __launch_bounds__(TPB) void seg_term_kernel(
    const int*    __restrict__ cls,     // [128]
    const float*  __restrict__ seg,     // [19*HW]
    const float*  __restrict__ boxes,   // [128*5]
    float*        __restrict__ out)     // [STUFF4*4 + 128*HW]
{
    const int b   = blockIdx.x;
    const int tid = threadIdx.x;
    const float4 z = make_float4(0.f, 0.f, 0.f, 0.f);

    if (b < STUFF_BLOCKS) {
        // ---- stuff copy: 8 batched loads, then 8 stores (MLP=8) ----
        const float4* s4 = reinterpret_cast<const float4*>(seg) + b * F4_PER_BLK;
        float4*       o4 = reinterpret_cast<float4*>(out)       + b * F4_PER_BLK;
        float4 v[ITEMS];
        #pragma unroll
        for (int k = 0; k < ITEMS; k++) v[k] = s4[tid + k * TPB];
        #pragma unroll
        for (int k = 0; k < ITEMS; k++) o4[tid + k * TPB] = v[k];
        return;
    }

    // ---- instance region: each block owns 16 rows of ONE plane ----
    const int ib  = b - STUFF_BLOCKS;
    const int n   = ib >> 4;                     // plane (16 blocks/plane)
    const int blk = ib & (BLOCKS_PER_PLANE - 1);
    const int r0  = blk * ROWS_PER_BLK;          // first row of this block

    float4* o4 = reinterpret_cast<float4*>(out) + STUFF4 + n * HW4 + blk * F4_PER_BLK;

    const int c = __ldg(cls + n);

    int x0 = 0, y0 = 0, x1 = 0, y1 = 0, m = 0;
    bool any = false;
    if (c != 0) {
        const float* bb = boxes + n * 5;
        x0 = (int)floorf(__ldg(bb + 1) * 0.25f);
        y0 = (int)floorf(__ldg(bb + 2) * 0.25f);
        x1 = (int)(rintf(__ldg(bb + 3) * 0.25f) + 1.0f);  // half-even, matches jnp.round
        y1 = (int)(rintf(__ldg(bb + 4) * 0.25f) + 1.0f);
        m  = (c + 10 > 18) ? 18 : c + 10;
        // does this block's row range [r0, r0+16) intersect [y0, y1)?
        any = (y1 > r0) && (y0 < r0 + ROWS_PER_BLK) && (x1 > x0) && (x1 > 0) && (x0 < WW);
    }

    if (!any) {
        // pure zero-fill burst
        #pragma unroll
        for (int k = 0; k < ITEMS; k++) o4[tid + k * TPB] = z;
        return;
    }

    const float4* s4 = reinterpret_cast<const float4*>(seg) + m * HW4 + blk * F4_PER_BLK;

    // Phase 1: compute all 8 values; loads batched up front by ptxas.
    float4 v[ITEMS];
    #pragma unroll
    for (int k = 0; k < ITEMS; k++) {
        const int idx = tid + k * TPB;           // float4 index within chunk
        const int y   = r0 + (idx >> 7);         // global row
        const int x   = (idx & (W4 - 1)) << 2;   // first col of this float4

        v[k] = z;
        if (y >= y0 && y < y1) {
            if (x >= x0 && (x + 3) < x1) {
                v[k] = s4[idx];                  // fully inside
            } else if ((x + 3) >= x0 && x < x1) {
                const float* sr = reinterpret_cast<const float*>(s4 + idx);
                float vv[4];
                #pragma unroll
                for (int j = 0; j < 4; j++) {
                    const int xx = x + j;
                    vv[j] = (xx >= x0 && xx < x1) ? sr[j] : 0.f;
                }
                v[k] = make_float4(vv[0], vv[1], vv[2], vv[3]);
            }
        }
    }
    // Phase 2: store burst
    #pragma unroll
    for (int k = 0; k < ITEMS; k++) o4[tid + k * TPB] = v[k];
}

extern "C" void kernel_launch(void* const* d_in, const int* in_sizes, int n_in,
                              void* d_out, int out_size)
{
    const int*   cls   = (const int*)d_in[0];
    const float* seg   = (const float*)d_in[1];
    const float* boxes = (const float*)d_in[2];
    float* out = (float*)d_out;

    const int blocks = STUFF_BLOCKS + NBOX * BLOCKS_PER_PLANE;  // 176 + 2048 = 2224
    seg_term_kernel<<<blocks, TPB>>>(cls, seg, boxes, out);
}